// round 16
// baseline (speedup 1.0000x reference)
#include <cuda_runtime.h>
#include <cuda_bf16.h>
#include <cstdint>

// ---------------------------------------------------------------------------
// HierarchicalBlockShuffleLayer (R15): R14 HMMA core, 64-row tiles, 4 CTAs/SM.
//   out_pair_p[64,64] = xn_pair_p[64,64] @ Wp[64,64] + bias,  p = 0..15
// Wp folds monarch (alpha*Wcol@Wrow^T) + flipped block-diag. Split bf16
// (x=hi+lo, W=hi+lo, 3 mma products, fp32 accum). M + Wp built in-CTA.
// Direct fragment STG with bias. 2 barriers/pair. 256 thr, 52.5KB smem ->
// 4 resident CTAs/SM for cross-CTA phase overlap.
// ---------------------------------------------------------------------------

#define THREADS 256

// smem byte offsets (tile = 64 rows)
#define S_AH   0          // 64 x 72 bf16 (A hi)    9216
#define S_AL   9216       // 64 x 72 bf16 (A lo)    9216
#define S_WH   18432      // 64 x 72 bf16 (W hi)    9216
#define S_WL   27648      // 64 x 72 bf16 (W lo)    9216
#define S_M    36864      // 32 x 32 f32            4096
#define S_GAM  40960
#define S_BET  45056
#define S_BIA  49152
#define S_MU   53248      // 64 f32
#define S_RS   53504      // 64 f32
#define SMEM_BYTES 53760

__device__ __forceinline__ void mma16816(float* c, const uint32_t* a,
                                         const uint32_t* b) {
    asm volatile(
        "mma.sync.aligned.m16n8k16.row.col.f32.bf16.bf16.f32 "
        "{%0,%1,%2,%3}, {%4,%5,%6,%7}, {%8,%9}, {%0,%1,%2,%3};"
        : "+f"(c[0]), "+f"(c[1]), "+f"(c[2]), "+f"(c[3])
        : "r"(a[0]), "r"(a[1]), "r"(a[2]), "r"(a[3]), "r"(b[0]), "r"(b[1]));
}

__global__ void __launch_bounds__(THREADS, 4)
hbsl_mma_kernel(const float* __restrict__ x,
                const float* __restrict__ gamma,
                const float* __restrict__ beta,
                const float* __restrict__ bw,
                const float* __restrict__ wrow,
                const float* __restrict__ wcol,
                const float* __restrict__ alphap,
                const float* __restrict__ bias,
                float* __restrict__ out) {
    extern __shared__ char sm[];
    uint32_t* AH32 = (uint32_t*)(sm + S_AH);
    uint32_t* AL32 = (uint32_t*)(sm + S_AL);
    uint32_t* WH32 = (uint32_t*)(sm + S_WH);
    uint32_t* WL32 = (uint32_t*)(sm + S_WL);
    float* Msm = (float*)(sm + S_M);
    float* GAM = (float*)(sm + S_GAM);
    float* BET = (float*)(sm + S_BET);
    float* BIA = (float*)(sm + S_BIA);
    float* MU  = (float*)(sm + S_MU);
    float* RS  = (float*)(sm + S_RS);

    const int t = threadIdx.x;
    const int w = t >> 5, l = t & 31;
    const size_t tbase = (size_t)blockIdx.x * 65536;   // 64 rows * 1024

    // stage gamma/beta/bias
    for (int i = t; i < 1024; i += THREADS) {
        GAM[i] = __ldg(gamma + i); BET[i] = __ldg(beta + i); BIA[i] = __ldg(bias + i);
    }
    // build alpha-folded monarch M[c][s] (4 entries/thread)
    {
        const float alpha = __ldg(alphap);
#pragma unroll
        for (int u = 0; u < 4; u++) {
            const int id = t + 256 * u;
            const int c = id >> 5, s = id & 31;
            float acc = 0.f;
#pragma unroll
            for (int j = 0; j < 32; j++)
                acc += __ldg(wcol + c * 32 + j) * __ldg(wrow + s * 32 + j);
            Msm[id] = alpha * acc;
        }
    }

    // ---- pass 1: LN stats (warp w -> rows 8w..8w+7), coalesced read ----
    {
        const float4* x4 = (const float4*)(x + tbase);
#pragma unroll 1
        for (int rr = 0; rr < 8; rr++) {
            const int row = 8 * w + rr;
            const float4* rp = x4 + (size_t)row * 256;
            float s = 0.f, sq = 0.f;
#pragma unroll
            for (int j = 0; j < 8; j++) {
                const float4 v = __ldg(rp + l + 32 * j);
                s  += v.x + v.y + v.z + v.w;
                sq += v.x * v.x + v.y * v.y + v.z * v.z + v.w * v.w;
            }
#pragma unroll
            for (int o = 16; o > 0; o >>= 1) {
                s  += __shfl_xor_sync(~0u, s,  o);
                sq += __shfl_xor_sync(~0u, sq, o);
            }
            if (l == 0) {
                const float mu = s * (1.f / 1024.f);
                MU[row] = mu;
                RS[row] = rsqrtf(sq * (1.f / 1024.f) - mu * mu + 1e-5f);
            }
        }
    }
    __syncthreads();

    const int m = t >> 2, qt = t & 3;          // convert roles (row, 16-dim group)
    const int gi = l >> 2, tig = l & 3;        // mma fragment roles
    const int rb = w & 3, nh = w >> 2;         // rowblock (16 rows), n-half

    // W-build role: thread -> row n = t>>2, k-dims 16*(t&3)..+15
    const int wn = t >> 2, wk0 = (t & 3) * 16;

    // ---- per-pair loop ----
    for (int p = 0; p < 16; p++) {
        const int q = 31 - p;

        // build W_p hi/lo in smem: 16 entries/thread
        {
            const int n = wn;
            const int s = (n < 32) ? n : (n - 32);
            const int off = (s < 16) ? 16 : 0;
            const int jj  = (s < 16) ? (15 - s) : (31 - s);
            const int rr  = (n < 32) ? p : q;
            const int grp = (s < 16) ? (63 - 2 * rr) : (62 - 2 * rr);
            uint32_t hw[8], lw[8];
#pragma unroll
            for (int i2 = 0; i2 < 8; i2++) {
                float wv2[2];
#pragma unroll
                for (int j2 = 0; j2 < 2; j2++) {
                    const int k = wk0 + i2 * 2 + j2;
                    float wv = 0.f;
                    const bool mon = (n < 32) ? (k < 32) : (k >= 32);
                    if (mon) {
                        const int c = (n < 32) ? k : (k - 32);
                        wv = Msm[c * 32 + s];
                    } else {
                        const int kk = (n < 32) ? (k - 32) : k;
                        const int b = kk - off;
                        if (b >= 0 && b < 16)
                            wv = __ldg(bw + grp * 256 + b * 16 + jj);
                    }
                    wv2[j2] = wv;
                }
                const __nv_bfloat16 h0 = __float2bfloat16(wv2[0]);
                const __nv_bfloat16 h1 = __float2bfloat16(wv2[1]);
                const __nv_bfloat16 e0 = __float2bfloat16(wv2[0] - __bfloat162float(h0));
                const __nv_bfloat16 e1 = __float2bfloat16(wv2[1] - __bfloat162float(h1));
                __nv_bfloat162 hh = __halves2bfloat162(h0, h1);
                __nv_bfloat162 ee = __halves2bfloat162(e0, e1);
                hw[i2] = *(uint32_t*)&hh;
                lw[i2] = *(uint32_t*)&ee;
            }
            const int wi = wn * 36 + (t & 3) * 8;    // uint32 index, stride 72 bf16
            *(uint4*)(WH32 + wi)     = make_uint4(hw[0], hw[1], hw[2], hw[3]);
            *(uint4*)(WH32 + wi + 4) = make_uint4(hw[4], hw[5], hw[6], hw[7]);
            *(uint4*)(WL32 + wi)     = make_uint4(lw[0], lw[1], lw[2], lw[3]);
            *(uint4*)(WL32 + wi + 4) = make_uint4(lw[4], lw[5], lw[6], lw[7]);
        }

        // convert A: thread -> (row m, 16 k-dims), LN + split bf16
        {
            const int dimb = (qt < 2) ? 32 * p + 16 * qt : 32 * q + 16 * (qt - 2);
            const float* xr = x + tbase + (size_t)m * 1024 + dimb;
            const float mu = MU[m], rs = RS[m];
            uint32_t hw[8], lw[8];
#pragma unroll
            for (int ii = 0; ii < 4; ii++) {
                const float4 v = __ldg((const float4*)xr + ii);
                const float* gp = GAM + dimb + 4 * ii;
                const float* bp = BET + dimb + 4 * ii;
                float xs[4];
                xs[0] = (v.x - mu) * rs * gp[0] + bp[0];
                xs[1] = (v.y - mu) * rs * gp[1] + bp[1];
                xs[2] = (v.z - mu) * rs * gp[2] + bp[2];
                xs[3] = (v.w - mu) * rs * gp[3] + bp[3];
#pragma unroll
                for (int c2 = 0; c2 < 2; c2++) {
                    const __nv_bfloat16 h0 = __float2bfloat16(xs[2 * c2]);
                    const __nv_bfloat16 h1 = __float2bfloat16(xs[2 * c2 + 1]);
                    const __nv_bfloat16 e0 = __float2bfloat16(xs[2 * c2]     - __bfloat162float(h0));
                    const __nv_bfloat16 e1 = __float2bfloat16(xs[2 * c2 + 1] - __bfloat162float(h1));
                    __nv_bfloat162 hh = __halves2bfloat162(h0, h1);
                    __nv_bfloat162 ee = __halves2bfloat162(e0, e1);
                    hw[ii * 2 + c2] = *(uint32_t*)&hh;
                    lw[ii * 2 + c2] = *(uint32_t*)&ee;
                }
            }
            const int wi = m * 36 + qt * 8;
            *(uint4*)(AH32 + wi)     = make_uint4(hw[0], hw[1], hw[2], hw[3]);
            *(uint4*)(AH32 + wi + 4) = make_uint4(hw[4], hw[5], hw[6], hw[7]);
            *(uint4*)(AL32 + wi)     = make_uint4(lw[0], lw[1], lw[2], lw[3]);
            *(uint4*)(AL32 + wi + 4) = make_uint4(lw[4], lw[5], lw[6], lw[7]);
        }
        __syncthreads();

        // ---- mma + direct store: warp = (rowblock rb, n-half nh) ----
        {
            float acc[4][4] = {};
            const int arow = (rb * 16 + gi) * 36 + tig;
#pragma unroll
            for (int ks = 0; ks < 4; ks++) {
                uint32_t ahi[4], alo[4];
                const int ai = arow + ks * 8;
                ahi[0] = AH32[ai];           ahi[1] = AH32[ai + 288];
                ahi[2] = AH32[ai + 4];       ahi[3] = AH32[ai + 292];
                alo[0] = AL32[ai];           alo[1] = AL32[ai + 288];
                alo[2] = AL32[ai + 4];       alo[3] = AL32[ai + 292];
#pragma unroll
                for (int nb = 0; nb < 4; nb++) {
                    const int bi = (nh * 32 + nb * 8 + gi) * 36 + ks * 8 + tig;
                    uint32_t bh[2], bl[2];
                    bh[0] = WH32[bi]; bh[1] = WH32[bi + 4];
                    bl[0] = WL32[bi]; bl[1] = WL32[bi + 4];
                    mma16816(acc[nb], ahi, bh);
                    mma16816(acc[nb], ahi, bl);
                    mma16816(acc[nb], alo, bh);
                }
            }
            // direct store with bias: quad covers a full 32B sector
            const int chunkb = nh ? 32 * q : 32 * p;
            const int row0 = rb * 16 + gi;
            float* ob0 = out + tbase + (size_t)row0 * 1024 + chunkb;
            float* ob1 = ob0 + 8 * 1024;
#pragma unroll
            for (int nb = 0; nb < 4; nb++) {
                const int cc = nb * 8 + tig * 2;
                const float2 bb = *(const float2*)(BIA + chunkb + cc);
                *(float2*)(ob0 + cc) = make_float2(acc[nb][0] + bb.x, acc[nb][1] + bb.y);
                *(float2*)(ob1 + cc) = make_float2(acc[nb][2] + bb.x, acc[nb][3] + bb.y);
            }
        }
        __syncthreads();   // A/W reused next pair
    }
}

// ---------------------------------------------------------------------------
extern "C" void kernel_launch(void* const* d_in, const int* in_sizes, int n_in,
                              void* d_out, int out_size) {
    const float* x     = (const float*)d_in[0];
    const float* gamma = (const float*)d_in[1];
    const float* beta  = (const float*)d_in[2];
    const float* bw    = (const float*)d_in[3];
    const float* wrow  = (const float*)d_in[4];
    const float* wcol  = (const float*)d_in[5];
    const float* alpha = (const float*)d_in[6];
    const float* bias  = (const float*)d_in[7];
    float* out = (float*)d_out;

    const int rows = in_sizes[0] / 1024;
    const int ntiles = rows / 64;              // 512 for the bench shape

    cudaFuncSetAttribute(hbsl_mma_kernel,
                         cudaFuncAttributeMaxDynamicSharedMemorySize, SMEM_BYTES);
    hbsl_mma_kernel<<<ntiles, THREADS, SMEM_BYTES>>>(x, gamma, beta, bw, wrow,
                                                     wcol, alpha, bias, out);
}

// round 17
// speedup vs baseline: 1.2213x; 1.2213x over previous
#include <cuda_runtime.h>
#include <cuda_bf16.h>
#include <cstdint>

// ---------------------------------------------------------------------------
// HierarchicalBlockShuffleLayer (R16): two-kernel split.
//  K1 (stats):  one warp/row streaming reduce -> g_stats[row] = {mu, rs}.
//  K2 (gemm):   grid = 16 pairs x 64 row-blocks. CTA owns pair p, 512 rows:
//               builds Wp ONCE (monarch+flip fold, split bf16), then 8 tiles
//               of 64 rows: convert (LN from g_stats, split bf16) -> mma.sync
//               (R13-validated fragments) -> direct fragment STG + bias.
//  x is read exactly twice total (stats + its own pair's columns), out once.
// ---------------------------------------------------------------------------

__device__ float2 g_stats[32768];     // {mu, rs} per row

// ---- K2 smem layout ----
#define S_AH    0          // 64 x 72 bf16 (A hi)   9216
#define S_AL    9216       // 64 x 72 bf16 (A lo)   9216
#define S_WH    18432      // 64 x 72 bf16 (W hi)   9216
#define S_WL    27648      // 64 x 72 bf16 (W lo)   9216
#define S_G2    36864      // 64 f32 (gamma slices)
#define S_B2    37120      // 64 f32 (beta slices)
#define S_BI2   37376      // 64 f32 (bias slices)
#define SMEM_BYTES 37632

__device__ __forceinline__ void mma16816(float* c, const uint32_t* a,
                                         const uint32_t* b) {
    asm volatile(
        "mma.sync.aligned.m16n8k16.row.col.f32.bf16.bf16.f32 "
        "{%0,%1,%2,%3}, {%4,%5,%6,%7}, {%8,%9}, {%0,%1,%2,%3};"
        : "+f"(c[0]), "+f"(c[1]), "+f"(c[2]), "+f"(c[3])
        : "r"(a[0]), "r"(a[1]), "r"(a[2]), "r"(a[3]), "r"(b[0]), "r"(b[1]));
}

// ---------------------------------------------------------------------------
__global__ void __launch_bounds__(512, 2)
stats_kernel(const float* __restrict__ x, int nrows) {
    const int w = threadIdx.x >> 5, l = threadIdx.x & 31;
    const int row = blockIdx.x * 16 + w;
    if (row >= nrows) return;
    const float4* rp = (const float4*)(x + (size_t)row * 1024);
    float s = 0.f, sq = 0.f;
#pragma unroll
    for (int j = 0; j < 8; j++) {
        const float4 v = __ldg(rp + l + 32 * j);
        s  += v.x + v.y + v.z + v.w;
        sq += v.x * v.x + v.y * v.y + v.z * v.z + v.w * v.w;
    }
#pragma unroll
    for (int o = 16; o > 0; o >>= 1) {
        s  += __shfl_xor_sync(~0u, s,  o);
        sq += __shfl_xor_sync(~0u, sq, o);
    }
    if (l == 0) {
        const float mu = s * (1.f / 1024.f);
        const float rs = rsqrtf(sq * (1.f / 1024.f) - mu * mu + 1e-5f);
        g_stats[row] = make_float2(mu, rs);
    }
}

// ---------------------------------------------------------------------------
__global__ void __launch_bounds__(256, 4)
gemm_kernel(const float* __restrict__ x,
            const float* __restrict__ gamma,
            const float* __restrict__ beta,
            const float* __restrict__ bw,
            const float* __restrict__ wrow,
            const float* __restrict__ wcol,
            const float* __restrict__ alphap,
            const float* __restrict__ bias,
            float* __restrict__ out,
            int rows_per_cta) {
    extern __shared__ char sm[];
    uint32_t* AH32 = (uint32_t*)(sm + S_AH);
    uint32_t* AL32 = (uint32_t*)(sm + S_AL);
    uint32_t* WH32 = (uint32_t*)(sm + S_WH);
    uint32_t* WL32 = (uint32_t*)(sm + S_WL);
    float* G2  = (float*)(sm + S_G2);
    float* B2  = (float*)(sm + S_B2);
    float* BI2 = (float*)(sm + S_BI2);
    float* MT  = (float*)(sm + S_AH);     // M scratch, overwritten by A later

    const int t = threadIdx.x;
    const int w = t >> 5, l = t & 31;
    const int p = blockIdx.x & 15;        // pair
    const int q = 31 - p;
    const size_t row0_cta = (size_t)(blockIdx.x >> 4) * rows_per_cta;

    // ---- one-time: stage slices, build M, build Wp ----
    if (t < 64) {
        const int chunk = (t < 32) ? 32 * p : 32 * q;
        const int d = chunk + (t & 31);
        G2[t] = __ldg(gamma + d); B2[t] = __ldg(beta + d); BI2[t] = __ldg(bias + d);
    }
    {
        const float alpha = __ldg(alphap);
#pragma unroll
        for (int u = 0; u < 4; u++) {
            const int id = t + 256 * u;
            const int c = id >> 5, s = id & 31;
            float acc = 0.f;
#pragma unroll
            for (int j = 0; j < 32; j++)
                acc += __ldg(wcol + c * 32 + j) * __ldg(wrow + s * 32 + j);
            MT[id] = alpha * acc;
        }
    }
    __syncthreads();
    {
        // W-build: thread -> row n = t>>2, k-dims 16*(t&3)..+15
        const int wn = t >> 2, wk0 = (t & 3) * 16;
        const int n = wn;
        const int s = (n < 32) ? n : (n - 32);
        const int off = (s < 16) ? 16 : 0;
        const int jj  = (s < 16) ? (15 - s) : (31 - s);
        const int rr  = (n < 32) ? p : q;
        const int grp = (s < 16) ? (63 - 2 * rr) : (62 - 2 * rr);
        uint32_t hw[8], lw[8];
#pragma unroll
        for (int i2 = 0; i2 < 8; i2++) {
            float wv2[2];
#pragma unroll
            for (int j2 = 0; j2 < 2; j2++) {
                const int k = wk0 + i2 * 2 + j2;
                float wv = 0.f;
                const bool mon = (n < 32) ? (k < 32) : (k >= 32);
                if (mon) {
                    const int c = (n < 32) ? k : (k - 32);
                    wv = MT[c * 32 + s];
                } else {
                    const int kk = (n < 32) ? (k - 32) : k;
                    const int b = kk - off;
                    if (b >= 0 && b < 16)
                        wv = __ldg(bw + grp * 256 + b * 16 + jj);
                }
                wv2[j2] = wv;
            }
            const __nv_bfloat16 h0 = __float2bfloat16(wv2[0]);
            const __nv_bfloat16 h1 = __float2bfloat16(wv2[1]);
            const __nv_bfloat16 e0 = __float2bfloat16(wv2[0] - __bfloat162float(h0));
            const __nv_bfloat16 e1 = __float2bfloat16(wv2[1] - __bfloat162float(h1));
            __nv_bfloat162 hh = __halves2bfloat162(h0, h1);
            __nv_bfloat162 ee = __halves2bfloat162(e0, e1);
            hw[i2] = *(uint32_t*)&hh;
            lw[i2] = *(uint32_t*)&ee;
        }
        const int wi = wn * 36 + (t & 3) * 8;
        *(uint4*)(WH32 + wi)     = make_uint4(hw[0], hw[1], hw[2], hw[3]);
        *(uint4*)(WH32 + wi + 4) = make_uint4(hw[4], hw[5], hw[6], hw[7]);
        *(uint4*)(WL32 + wi)     = make_uint4(lw[0], lw[1], lw[2], lw[3]);
        *(uint4*)(WL32 + wi + 4) = make_uint4(lw[4], lw[5], lw[6], lw[7]);
    }
    __syncthreads();   // MT dead; A buffer free

    const int m = t >> 2, qt = t & 3;          // convert roles
    const int gi = l >> 2, tig = l & 3;        // mma fragment roles
    const int rb = w & 3, nh = w >> 2;         // rowblock, n-half
    const int dloc  = (qt < 2) ? 16 * qt : 32 + 16 * (qt - 2);
    const int dimbg = (qt < 2) ? 32 * p + 16 * qt : 32 * q + 16 * (qt - 2);

    const int ntile = rows_per_cta >> 6;
    for (int tile = 0; tile < ntile; tile++) {
        const size_t rowb = row0_cta + (size_t)tile * 64;

        // ---- convert A: thread -> (row m, 16 k-dims) ----
        {
            const size_t grow = rowb + m;
            const float2 st = g_stats[grow];
            const float mu = st.x, rs = st.y;
            const float* xr = x + grow * 1024 + dimbg;
            uint32_t hw[8], lw[8];
#pragma unroll
            for (int ii = 0; ii < 4; ii++) {
                const float4 v = __ldg((const float4*)xr + ii);
                const float* gp = G2 + dloc + 4 * ii;
                const float* bp = B2 + dloc + 4 * ii;
                float xs[4];
                xs[0] = (v.x - mu) * rs * gp[0] + bp[0];
                xs[1] = (v.y - mu) * rs * gp[1] + bp[1];
                xs[2] = (v.z - mu) * rs * gp[2] + bp[2];
                xs[3] = (v.w - mu) * rs * gp[3] + bp[3];
#pragma unroll
                for (int c2 = 0; c2 < 2; c2++) {
                    const __nv_bfloat16 h0 = __float2bfloat16(xs[2 * c2]);
                    const __nv_bfloat16 h1 = __float2bfloat16(xs[2 * c2 + 1]);
                    const __nv_bfloat16 e0 = __float2bfloat16(xs[2 * c2]     - __bfloat162float(h0));
                    const __nv_bfloat16 e1 = __float2bfloat16(xs[2 * c2 + 1] - __bfloat162float(h1));
                    __nv_bfloat162 hh = __halves2bfloat162(h0, h1);
                    __nv_bfloat162 ee = __halves2bfloat162(e0, e1);
                    hw[ii * 2 + c2] = *(uint32_t*)&hh;
                    lw[ii * 2 + c2] = *(uint32_t*)&ee;
                }
            }
            const int wi = m * 36 + qt * 8;
            *(uint4*)(AH32 + wi)     = make_uint4(hw[0], hw[1], hw[2], hw[3]);
            *(uint4*)(AH32 + wi + 4) = make_uint4(hw[4], hw[5], hw[6], hw[7]);
            *(uint4*)(AL32 + wi)     = make_uint4(lw[0], lw[1], lw[2], lw[3]);
            *(uint4*)(AL32 + wi + 4) = make_uint4(lw[4], lw[5], lw[6], lw[7]);
        }
        __syncthreads();

        // ---- mma + direct store ----
        {
            float acc[4][4] = {};
            const int arow = (rb * 16 + gi) * 36 + tig;
#pragma unroll
            for (int ks = 0; ks < 4; ks++) {
                uint32_t ahi[4], alo[4];
                const int ai = arow + ks * 8;
                ahi[0] = AH32[ai];           ahi[1] = AH32[ai + 288];
                ahi[2] = AH32[ai + 4];       ahi[3] = AH32[ai + 292];
                alo[0] = AL32[ai];           alo[1] = AL32[ai + 288];
                alo[2] = AL32[ai + 4];       alo[3] = AL32[ai + 292];
#pragma unroll
                for (int nb = 0; nb < 4; nb++) {
                    const int bi = (nh * 32 + nb * 8 + gi) * 36 + ks * 8 + tig;
                    uint32_t bh[2], bl[2];
                    bh[0] = WH32[bi]; bh[1] = WH32[bi + 4];
                    bl[0] = WL32[bi]; bl[1] = WL32[bi + 4];
                    mma16816(acc[nb], ahi, bh);
                    mma16816(acc[nb], ahi, bl);
                    mma16816(acc[nb], alo, bh);
                }
            }
            const int chunkg = nh ? 32 * q : 32 * p;
            const int bofs   = nh ? 32 : 0;
            const int row0 = rb * 16 + gi;
            float* ob0 = out + (rowb + row0) * 1024 + chunkg;
            float* ob1 = ob0 + 8 * 1024;
#pragma unroll
            for (int nb = 0; nb < 4; nb++) {
                const int cc = nb * 8 + tig * 2;
                const float2 bb = *(const float2*)(BI2 + bofs + cc);
                *(float2*)(ob0 + cc) = make_float2(acc[nb][0] + bb.x, acc[nb][1] + bb.y);
                *(float2*)(ob1 + cc) = make_float2(acc[nb][2] + bb.x, acc[nb][3] + bb.y);
            }
        }
        __syncthreads();   // A reused next tile
    }
}

// ---------------------------------------------------------------------------
extern "C" void kernel_launch(void* const* d_in, const int* in_sizes, int n_in,
                              void* d_out, int out_size) {
    const float* x     = (const float*)d_in[0];
    const float* gamma = (const float*)d_in[1];
    const float* beta  = (const float*)d_in[2];
    const float* bw    = (const float*)d_in[3];
    const float* wrow  = (const float*)d_in[4];
    const float* wcol  = (const float*)d_in[5];
    const float* alpha = (const float*)d_in[6];
    const float* bias  = (const float*)d_in[7];
    float* out = (float*)d_out;

    const int rows = in_sizes[0] / 1024;       // 32768

    stats_kernel<<<(rows + 15) / 16, 512>>>(x, rows);

    const int nblocks = 64;                    // row blocks per pair
    const int rows_per_cta = rows / nblocks;   // 512
    cudaFuncSetAttribute(gemm_kernel,
                         cudaFuncAttributeMaxDynamicSharedMemorySize, SMEM_BYTES);
    gemm_kernel<<<16 * nblocks, 256, SMEM_BYTES>>>(x, gamma, beta, bw, wrow,
                                                   wcol, alpha, bias, out,
                                                   rows_per_cta);
}